// round 10
// baseline (speedup 1.0000x reference)
#include <cuda_runtime.h>
#include <mma.h>

using namespace nvcuda;

#define NQ_MAX 50000
#define NC 128
#define NG 8
#define NS 16

// Padded by 128 rows: partial-tile wmma stores at the M edge write into the
// pad instead of the neighboring buffer.
__device__ float g_q[(NQ_MAX + 128) * NC];
__device__ float g_k[(NQ_MAX + 128) * NC];
__device__ float g_v[(NQ_MAX + 128) * NC];

__device__ __forceinline__ void cp16(unsigned dst, const void* src, bool pred) {
    asm volatile("cp.async.ca.shared.global [%0], [%1], 16, %2;"
                 :: "r"(dst), "l"(src), "r"(pred ? 16 : 0));
}

// ---------------------------------------------------------------------------
// Projection GEMM (tf32 tensor cores), cp.async A double-buffer, B resident.
// Y[m,c] = sum_k X[m,k] * W[c,k]   (biases folded into attn kernel)
// Block tile 128x128, BK=32 (4 stages), 8 warps 4(M)x2(N), warp 32x64.
// fp32 inputs fed to tf32 HMMA directly (HW truncation; no cvt on the path).
// Dynamic smem: A 2x(128x36) + B (128x132) floats = 104448 bytes.
// ---------------------------------------------------------------------------
#define LDKA 36    // A row pitch (floats); 144B = 9x16B
#define LDKB 132   // B row pitch (floats); 528B = 33x16B
#define A_BUF_FLOATS (128 * LDKA)

__global__ void __launch_bounds__(256) proj_kernel(
    const float* __restrict__ x, const float* __restrict__ x2,
    const float* __restrict__ Wq, const float* __restrict__ Wk,
    const float* __restrict__ Wv,
    int n, int n2)
{
    const float *X, *W;
    float* Y;
    int M;
    if (blockIdx.y == 0)      { X = x;  W = Wq; Y = g_q; M = n;  }
    else if (blockIdx.y == 1) { X = x2; W = Wk; Y = g_k; M = n2; }
    else                      { X = x2; W = Wv; Y = g_v; M = n2; }

    extern __shared__ float smem[];
    float* As = smem;                       // 2 x 128 x LDKA
    float* Bs = smem + 2 * A_BUF_FLOATS;    // 128 x LDKB

    const int t = threadIdx.x;
    const int block_m = blockIdx.x * 128;
    if (block_m >= M) return;

    const int warp = t >> 5;
    const int wm = (warp & 3) * 32;
    const int wn = (warp >> 2) * 64;

    const unsigned sA = (unsigned)__cvta_generic_to_shared(As);
    const unsigned sB = (unsigned)__cvta_generic_to_shared(Bs);

    // ---- prologue: full B (128x128) + A stage 0, one commit group ----
    {
        // B: 4096 float4, 16 per thread
#pragma unroll
        for (int it = 0; it < 16; it++) {
            int lin = it * 256 + t;
            int r = lin >> 5;               // 0..127 (c row)
            int cf = (lin & 31) << 2;       // float col 0..124
            cp16(sB + (unsigned)((r * LDKB + cf) * 4),
                 W + (size_t)r * 128 + cf, true);
        }
        // A stage 0: 1024 float4, 4 per thread
#pragma unroll
        for (int it = 0; it < 4; it++) {
            int lin = it * 256 + t;
            int r = lin >> 3;               // 0..127
            int cf = (lin & 7) << 2;        // 0..28
            int gr = block_m + r;
            cp16(sA + (unsigned)((r * LDKA + cf) * 4),
                 X + (size_t)gr * 128 + cf, gr < M);
        }
        asm volatile("cp.async.commit_group;");
    }

    wmma::fragment<wmma::accumulator, 16, 16, 8, float> acc[2][4];
#pragma unroll
    for (int i = 0; i < 2; i++)
#pragma unroll
        for (int j = 0; j < 4; j++) wmma::fill_fragment(acc[i][j], 0.0f);

#pragma unroll
    for (int s = 0; s < 4; s++) {
        asm volatile("cp.async.wait_group 0;");
        __syncthreads();

        if (s < 3) {
            const int k0n = (s + 1) * 32;
            const unsigned bufo = (unsigned)(((s + 1) & 1) * A_BUF_FLOATS * 4);
#pragma unroll
            for (int it = 0; it < 4; it++) {
                int lin = it * 256 + t;
                int r = lin >> 3;
                int cf = (lin & 7) << 2;
                int gr = block_m + r;
                cp16(sA + bufo + (unsigned)((r * LDKA + cf) * 4),
                     X + (size_t)gr * 128 + k0n + cf, gr < M);
            }
            asm volatile("cp.async.commit_group;");
        }

        const float* Ab = As + (s & 1) * A_BUF_FLOATS;
        const int k0 = s * 32;
#pragma unroll
        for (int kk = 0; kk < 32; kk += 8) {
            wmma::fragment<wmma::matrix_a, 16, 16, 8, wmma::precision::tf32, wmma::row_major> a[2];
            wmma::fragment<wmma::matrix_b, 16, 16, 8, wmma::precision::tf32, wmma::col_major> b[4];
#pragma unroll
            for (int i = 0; i < 2; i++)
                wmma::load_matrix_sync(a[i], Ab + (wm + i * 16) * LDKA + kk, LDKA);
#pragma unroll
            for (int j = 0; j < 4; j++)
                wmma::load_matrix_sync(b[j], Bs + (wn + j * 16) * LDKB + k0 + kk, LDKB);
#pragma unroll
            for (int i = 0; i < 2; i++)
#pragma unroll
                for (int j = 0; j < 4; j++)
                    wmma::mma_sync(acc[i][j], a[i], b[j], acc[i][j]);
        }
    }

#pragma unroll
    for (int i = 0; i < 2; i++)
#pragma unroll
        for (int j = 0; j < 4; j++)
            wmma::store_matrix_sync(
                Y + (size_t)(block_m + wm + i * 16) * 128 + wn + j * 16,
                acc[i][j], 128, wmma::mem_row_major);
}

// ---------------------------------------------------------------------------
// Fused gather + positional MLP + grouped attention.
// One warp per query. Lane l -> channels [4l,4l+4), group g = l>>2.
// Neighbor MLP hidden computed once by lane (l&15), fetched via shfl.
// NEW: group-uniform terms folded pre-butterfly (butterfly(t+c/4) =
// butterfly(t)+c), so loop 1 has NO reduction shfls; all 32 shfl_xor run as
// 16 independent 2-chains in a batch loop (latency overlapped).
// ---------------------------------------------------------------------------
__global__ void __launch_bounds__(256) attn_kernel(
    const float* __restrict__ p, const float* __restrict__ p2,
    const int* __restrict__ idx,
    const float* __restrict__ bq, const float* __restrict__ bk,
    const float* __restrict__ bv,
    const float* __restrict__ W1, const float* __restrict__ b1,
    const float* __restrict__ bng, const float* __restrict__ bnb,
    const float* __restrict__ bnm, const float* __restrict__ bnv,
    const float* __restrict__ W2, const float* __restrict__ b2,
    float* __restrict__ out, int n)
{
    __shared__ float sA[9];
    __shared__ float sc[3];
    __shared__ float sW2[16][3];
    __shared__ float sb2[16];
    __shared__ float sBg[8];

    const int t = threadIdx.x;
    if (t < 9) {
        int r = t / 3;
        float s = bng[r] * rsqrtf(bnv[r] + 1e-5f);
        sA[t] = s * W1[t];
    }
    if (t < 3) sc[t] = bng[t] * rsqrtf(bnv[t] + 1e-5f) * (b1[t] - bnm[t]) + bnb[t];
    if (t < 48) sW2[t / 3][t % 3] = W2[t];
    if (t < 16) sb2[t] = b2[t];
    if (t < 8) {
        float s = 0.f;
#pragma unroll
        for (int c = 0; c < 16; c++) s += bk[t * 16 + c];
        sBg[t] = s;
    }
    __syncthreads();

    const int warp = t >> 5;
    const int lane = t & 31;
    const int i = blockIdx.x * 8 + warp;
    if (i >= n) return;

    const int g = lane >> 2;
    const float w2q0 = sW2[g][0], w2q1 = sW2[g][1], w2q2 = sW2[g][2], b2q = sb2[g];
    const float w2k0 = sW2[8 + g][0], w2k1 = sW2[8 + g][1], w2k2 = sW2[8 + g][2], b2k = sb2[8 + g];
    const float Bg = sBg[g];

    float4 q4 = *(const float4*)(g_q + (size_t)i * 128 + lane * 4);
    {
        const float4 bq4 = *(const float4*)(bq + lane * 4);
        q4.x += bq4.x; q4.y += bq4.y; q4.z += bq4.z; q4.w += bq4.w;
    }

    float qs, beta;
    {
        const float4 bk4 = *(const float4*)(bk + lane * 4);
        qs   = q4.x + q4.y + q4.z + q4.w;
        beta = bk4.x * q4.x + bk4.y * q4.y + bk4.z * q4.z + bk4.w * q4.w;
        qs   += __shfl_xor_sync(0xffffffffu, qs, 1);
        beta += __shfl_xor_sync(0xffffffffu, beta, 1);
        qs   += __shfl_xor_sync(0xffffffffu, qs, 2);
        beta += __shfl_xor_sync(0xffffffffu, beta, 2);
    }

    int nb[16];
    {
        const int4* ip = (const int4*)(idx + (size_t)i * 16);
#pragma unroll
        for (int s4 = 0; s4 < 4; s4++) {
            int4 v = ip[s4];
            nb[s4 * 4 + 0] = v.x; nb[s4 * 4 + 1] = v.y;
            nb[s4 * 4 + 2] = v.z; nb[s4 * 4 + 3] = v.w;
        }
    }

    // per-neighbor MLP hidden, computed once by lane (l & 15)
    float h0, h1, h2;
    {
        const float px = p[i * 3 + 0], py = p[i * 3 + 1], pz = p[i * 3 + 2];
        const int jm = nb[lane & 15];
        const float rx = p2[jm * 3 + 0] - px;
        const float ry = p2[jm * 3 + 1] - py;
        const float rz = p2[jm * 3 + 2] - pz;
        h0 = fmaxf(fmaf(sA[0], rx, fmaf(sA[1], ry, fmaf(sA[2], rz, sc[0]))), 0.f);
        h1 = fmaxf(fmaf(sA[3], rx, fmaf(sA[4], ry, fmaf(sA[5], rz, sc[1]))), 0.f);
        h2 = fmaxf(fmaf(sA[6], rx, fmaf(sA[7], ry, fmaf(sA[8], rz, sc[2]))), 0.f);
    }

    // loop 1: per-lane partials, no reduction shfls
    float tl[16];
#pragma unroll
    for (int s = 0; s < 16; s++) {
        const int j = nb[s];
        const float4 k4 = *(const float4*)(g_k + (size_t)j * 128 + lane * 4);
        float kq = k4.x * q4.x + k4.y * q4.y + k4.z * q4.z + k4.w * q4.w;
        float ks = k4.x + k4.y + k4.z + k4.w;

        const float h0s = __shfl_sync(0xffffffffu, h0, s);
        const float h1s = __shfl_sync(0xffffffffu, h1, s);
        const float h2s = __shfl_sync(0xffffffffu, h2, s);
        const float prq = fmaf(w2q0, h0s, fmaf(w2q1, h1s, fmaf(w2q2, h2s, b2q)));
        const float prk = fmaf(w2k0, h0s, fmaf(w2k1, h1s, fmaf(w2k2, h2s, b2k)));

        const float c = beta + prq * Bg + prk * fmaf(16.f, prq, qs);
        tl[s] = fmaf(prq, ks, kq) + 0.25f * c;
    }

    // loop 2: 16 independent 2-deep butterfly chains (latency overlapped)
#pragma unroll
    for (int s = 0; s < 16; s++) {
        float a = tl[s] + __shfl_xor_sync(0xffffffffu, tl[s], 1);
        tl[s] = a + __shfl_xor_sync(0xffffffffu, a, 2);
    }

    float mx = 0.25f * tl[0];
#pragma unroll
    for (int s = 1; s < 16; s++) mx = fmaxf(mx, 0.25f * tl[s]);
    float denom = 0.f;
    float w[16];
#pragma unroll
    for (int s = 0; s < 16; s++) {
        w[s] = __expf(0.25f * tl[s] - mx);
        denom += w[s];
    }
    const float inv = 1.f / denom;

    float4 o = make_float4(0.f, 0.f, 0.f, 0.f);
#pragma unroll
    for (int s = 0; s < 16; s++) {
        const float ws = w[s] * inv;
        const float4 v4 = *(const float4*)(g_v + (size_t)nb[s] * 128 + lane * 4);
        o.x = fmaf(ws, v4.x, o.x);
        o.y = fmaf(ws, v4.y, o.y);
        o.z = fmaf(ws, v4.z, o.z);
        o.w = fmaf(ws, v4.w, o.w);
    }
    const float4 bv4 = *(const float4*)(bv + lane * 4);
    o.x += bv4.x; o.y += bv4.y; o.z += bv4.z; o.w += bv4.w;
    *(float4*)(out + (size_t)i * 128 + lane * 4) = o;
}

extern "C" void kernel_launch(void* const* d_in, const int* in_sizes, int n_in,
                              void* d_out, int out_size)
{
    const float* p   = (const float*)d_in[0];
    const float* x   = (const float*)d_in[1];
    const float* p2  = (const float*)d_in[2];
    const float* x2  = (const float*)d_in[3];
    const int*   idx = (const int*)d_in[4];
    const float* Wq  = (const float*)d_in[5];
    const float* bq  = (const float*)d_in[6];
    const float* Wk  = (const float*)d_in[7];
    const float* bk  = (const float*)d_in[8];
    const float* Wv  = (const float*)d_in[9];
    const float* bv  = (const float*)d_in[10];
    const float* W1  = (const float*)d_in[11];
    const float* b1  = (const float*)d_in[12];
    const float* bng = (const float*)d_in[13];
    const float* bnb = (const float*)d_in[14];
    const float* bnm = (const float*)d_in[15];
    const float* bnv = (const float*)d_in[16];
    const float* W2  = (const float*)d_in[17];
    const float* b2  = (const float*)d_in[18];
    float* out = (float*)d_out;

    const int n  = in_sizes[1] / NC;
    const int n2 = in_sizes[3] / NC;
    const int mmax = n > n2 ? n : n2;

    const int smem_bytes = (2 * A_BUF_FLOATS + 128 * LDKB) * 4;   // 104448
    static int attr_set = 0;
    if (!attr_set) {
        cudaFuncSetAttribute(proj_kernel,
                             cudaFuncAttributeMaxDynamicSharedMemorySize,
                             smem_bytes);
        attr_set = 1;
    }

    dim3 pg((mmax + 127) / 128, 3);
    proj_kernel<<<pg, 256, smem_bytes>>>(x, x2, Wq, Wk, Wv, n, n2);
    attn_kernel<<<(n + 7) / 8, 256>>>(p, p2, idx, bq, bk, bv,
                                      W1, b1, bng, bnb, bnm, bnv,
                                      W2, b2, out, n);
}

// round 11
// speedup vs baseline: 1.0271x; 1.0271x over previous
#include <cuda_runtime.h>
#include <mma.h>

using namespace nvcuda;

#define NQ_MAX 50000
#define NC 128
#define NG 8
#define NS 16

// Padded by 128 rows: partial-tile wmma stores at the M edge write into the
// pad instead of the neighboring buffer.
__device__ float g_q[(NQ_MAX + 128) * NC];
__device__ float g_k[(NQ_MAX + 128) * NC];
__device__ float g_v[(NQ_MAX + 128) * NC];

__device__ __forceinline__ float to_tf32(float x) {
    float r;
    asm("cvt.rna.tf32.f32 %0, %1;" : "=f"(r) : "f"(x));
    return r;
}

// ---------------------------------------------------------------------------
// Projection GEMM (tf32 tensor cores), BK=64: only 2 load/sync phases.
// Y[m,c] = sum_k X[m,k] * W[c,k]   (biases folded into attn kernel)
// Block tile 128x128, 8 warps 4(M)x2(N), warp tile 32x64.
// Dynamic smem: 2 x 128 x 68 floats = 69632 bytes.
// ---------------------------------------------------------------------------
#define LDA 68   // 64 data + 4 pad floats per row

__global__ void __launch_bounds__(256) proj_kernel(
    const float* __restrict__ x, const float* __restrict__ x2,
    const float* __restrict__ Wq, const float* __restrict__ Wk,
    const float* __restrict__ Wv,
    int n, int n2)
{
    const float *X, *W;
    float* Y;
    int M;
    if (blockIdx.y == 0)      { X = x;  W = Wq; Y = g_q; M = n;  }
    else if (blockIdx.y == 1) { X = x2; W = Wk; Y = g_k; M = n2; }
    else                      { X = x2; W = Wv; Y = g_v; M = n2; }

    extern __shared__ float smem[];
    float* As = smem;              // 128 x LDA
    float* Bs = smem + 128 * LDA;  // 128 x LDA

    const int t = threadIdx.x;
    const int block_m = blockIdx.x * 128;
    if (block_m >= M) return;

    const int warp = t >> 5;
    const int wm = (warp & 3) * 32;
    const int wn = (warp >> 2) * 64;

    wmma::fragment<wmma::accumulator, 16, 16, 8, float> acc[2][4];
#pragma unroll
    for (int i = 0; i < 2; i++)
#pragma unroll
        for (int j = 0; j < 4; j++) wmma::fill_fragment(acc[i][j], 0.0f);

    for (int k0 = 0; k0 < 128; k0 += 64) {
        // Stage A (128x64) and B (128x64): 2048 float4 each, 8 per thread.
#pragma unroll
        for (int it = 0; it < 8; it++) {
            int lin = it * 256 + t;
            int r = lin >> 4;            // 0..127
            int c4 = (lin & 15) << 2;    // 0..60
            int gr = block_m + r;
            float4 xv = make_float4(0.f, 0.f, 0.f, 0.f);
            if (gr < M) xv = *(const float4*)(X + (size_t)gr * 128 + k0 + c4);
            As[r * LDA + c4 + 0] = to_tf32(xv.x);
            As[r * LDA + c4 + 1] = to_tf32(xv.y);
            As[r * LDA + c4 + 2] = to_tf32(xv.z);
            As[r * LDA + c4 + 3] = to_tf32(xv.w);
            float4 wv = *(const float4*)(W + (size_t)r * 128 + k0 + c4);
            Bs[r * LDA + c4 + 0] = to_tf32(wv.x);
            Bs[r * LDA + c4 + 1] = to_tf32(wv.y);
            Bs[r * LDA + c4 + 2] = to_tf32(wv.z);
            Bs[r * LDA + c4 + 3] = to_tf32(wv.w);
        }
        __syncthreads();

#pragma unroll
        for (int kk = 0; kk < 64; kk += 8) {
            wmma::fragment<wmma::matrix_a, 16, 16, 8, wmma::precision::tf32, wmma::row_major> a[2];
            wmma::fragment<wmma::matrix_b, 16, 16, 8, wmma::precision::tf32, wmma::col_major> b[4];
#pragma unroll
            for (int i = 0; i < 2; i++)
                wmma::load_matrix_sync(a[i], As + (wm + i * 16) * LDA + kk, LDA);
#pragma unroll
            for (int j = 0; j < 4; j++)
                wmma::load_matrix_sync(b[j], Bs + (wn + j * 16) * LDA + kk, LDA);
#pragma unroll
            for (int i = 0; i < 2; i++)
#pragma unroll
                for (int j = 0; j < 4; j++)
                    wmma::mma_sync(acc[i][j], a[i], b[j], acc[i][j]);
        }
        __syncthreads();
    }

#pragma unroll
    for (int i = 0; i < 2; i++)
#pragma unroll
        for (int j = 0; j < 4; j++)
            wmma::store_matrix_sync(
                Y + (size_t)(block_m + wm + i * 16) * 128 + wn + j * 16,
                acc[i][j], 128, wmma::mem_row_major);
}

// ---------------------------------------------------------------------------
// Fused gather + positional MLP + grouped attention (R9 structure, 83.3us,
// + occupancy clamp). One warp per query. Lane l -> channels [4l,4l+4),
// group g = l>>2. Neighbor MLP hidden computed once by lane (l&15), fetched
// via shfl; butterfly kept INLINE per neighbor (scheduler interleaves
// adjacent iterations).
// ---------------------------------------------------------------------------
__global__ void __launch_bounds__(256, 4) attn_kernel(
    const float* __restrict__ p, const float* __restrict__ p2,
    const int* __restrict__ idx,
    const float* __restrict__ bq, const float* __restrict__ bk,
    const float* __restrict__ bv,
    const float* __restrict__ W1, const float* __restrict__ b1,
    const float* __restrict__ bng, const float* __restrict__ bnb,
    const float* __restrict__ bnm, const float* __restrict__ bnv,
    const float* __restrict__ W2, const float* __restrict__ b2,
    float* __restrict__ out, int n)
{
    __shared__ float sA[9];
    __shared__ float sc[3];
    __shared__ float sW2[16][3];
    __shared__ float sb2[16];
    __shared__ float sBg[8];

    const int t = threadIdx.x;
    if (t < 9) {
        int r = t / 3;
        float s = bng[r] * rsqrtf(bnv[r] + 1e-5f);
        sA[t] = s * W1[t];
    }
    if (t < 3) sc[t] = bng[t] * rsqrtf(bnv[t] + 1e-5f) * (b1[t] - bnm[t]) + bnb[t];
    if (t < 48) sW2[t / 3][t % 3] = W2[t];
    if (t < 16) sb2[t] = b2[t];
    if (t < 8) {
        float s = 0.f;
#pragma unroll
        for (int c = 0; c < 16; c++) s += bk[t * 16 + c];
        sBg[t] = s;
    }
    __syncthreads();

    const int warp = t >> 5;
    const int lane = t & 31;
    const int i = blockIdx.x * 8 + warp;
    if (i >= n) return;

    const int g = lane >> 2;
    const float w2q0 = sW2[g][0], w2q1 = sW2[g][1], w2q2 = sW2[g][2], b2q = sb2[g];
    const float w2k0 = sW2[8 + g][0], w2k1 = sW2[8 + g][1], w2k2 = sW2[8 + g][2], b2k = sb2[8 + g];
    const float Bg = sBg[g];

    float4 q4 = *(const float4*)(g_q + (size_t)i * 128 + lane * 4);
    {
        const float4 bq4 = *(const float4*)(bq + lane * 4);
        q4.x += bq4.x; q4.y += bq4.y; q4.z += bq4.z; q4.w += bq4.w;
    }

    float qs, beta;
    {
        const float4 bk4 = *(const float4*)(bk + lane * 4);
        qs   = q4.x + q4.y + q4.z + q4.w;
        beta = bk4.x * q4.x + bk4.y * q4.y + bk4.z * q4.z + bk4.w * q4.w;
        qs   += __shfl_xor_sync(0xffffffffu, qs, 1);
        beta += __shfl_xor_sync(0xffffffffu, beta, 1);
        qs   += __shfl_xor_sync(0xffffffffu, qs, 2);
        beta += __shfl_xor_sync(0xffffffffu, beta, 2);
    }

    int nb[16];
    {
        const int4* ip = (const int4*)(idx + (size_t)i * 16);
#pragma unroll
        for (int s4 = 0; s4 < 4; s4++) {
            int4 v = ip[s4];
            nb[s4 * 4 + 0] = v.x; nb[s4 * 4 + 1] = v.y;
            nb[s4 * 4 + 2] = v.z; nb[s4 * 4 + 3] = v.w;
        }
    }

    // per-neighbor MLP hidden, computed once by lane (l & 15)
    float h0, h1, h2;
    {
        const float px = p[i * 3 + 0], py = p[i * 3 + 1], pz = p[i * 3 + 2];
        const int jm = nb[lane & 15];
        const float rx = p2[jm * 3 + 0] - px;
        const float ry = p2[jm * 3 + 1] - py;
        const float rz = p2[jm * 3 + 2] - pz;
        h0 = fmaxf(fmaf(sA[0], rx, fmaf(sA[1], ry, fmaf(sA[2], rz, sc[0]))), 0.f);
        h1 = fmaxf(fmaf(sA[3], rx, fmaf(sA[4], ry, fmaf(sA[5], rz, sc[1]))), 0.f);
        h2 = fmaxf(fmaf(sA[6], rx, fmaf(sA[7], ry, fmaf(sA[8], rz, sc[2]))), 0.f);
    }

    float logit[16];
#pragma unroll
    for (int s = 0; s < 16; s++) {
        const int j = nb[s];
        const float4 k4 = *(const float4*)(g_k + (size_t)j * 128 + lane * 4);
        float kq = k4.x * q4.x + k4.y * q4.y + k4.z * q4.z + k4.w * q4.w;
        float ks = k4.x + k4.y + k4.z + k4.w;

        const float h0s = __shfl_sync(0xffffffffu, h0, s);
        const float h1s = __shfl_sync(0xffffffffu, h1, s);
        const float h2s = __shfl_sync(0xffffffffu, h2, s);
        const float prq = fmaf(w2q0, h0s, fmaf(w2q1, h1s, fmaf(w2q2, h2s, b2q)));
        const float prk = fmaf(w2k0, h0s, fmaf(w2k1, h1s, fmaf(w2k2, h2s, b2k)));

        float u = fmaf(prq, ks, kq);
        u += __shfl_xor_sync(0xffffffffu, u, 1);
        u += __shfl_xor_sync(0xffffffffu, u, 2);

        logit[s] = 0.25f * (u + beta + prq * Bg + prk * fmaf(16.f, prq, qs));
    }

    float mx = logit[0];
#pragma unroll
    for (int s = 1; s < 16; s++) mx = fmaxf(mx, logit[s]);
    float denom = 0.f;
#pragma unroll
    for (int s = 0; s < 16; s++) {
        logit[s] = __expf(logit[s] - mx);
        denom += logit[s];
    }
    const float inv = 1.f / denom;

    float4 o = make_float4(0.f, 0.f, 0.f, 0.f);
#pragma unroll
    for (int s = 0; s < 16; s++) {
        const float w = logit[s] * inv;
        const float4 v4 = *(const float4*)(g_v + (size_t)nb[s] * 128 + lane * 4);
        o.x = fmaf(w, v4.x, o.x);
        o.y = fmaf(w, v4.y, o.y);
        o.z = fmaf(w, v4.z, o.z);
        o.w = fmaf(w, v4.w, o.w);
    }
    const float4 bv4 = *(const float4*)(bv + lane * 4);
    o.x += bv4.x; o.y += bv4.y; o.z += bv4.z; o.w += bv4.w;
    *(float4*)(out + (size_t)i * 128 + lane * 4) = o;
}

extern "C" void kernel_launch(void* const* d_in, const int* in_sizes, int n_in,
                              void* d_out, int out_size)
{
    const float* p   = (const float*)d_in[0];
    const float* x   = (const float*)d_in[1];
    const float* p2  = (const float*)d_in[2];
    const float* x2  = (const float*)d_in[3];
    const int*   idx = (const int*)d_in[4];
    const float* Wq  = (const float*)d_in[5];
    const float* bq  = (const float*)d_in[6];
    const float* Wk  = (const float*)d_in[7];
    const float* bk  = (const float*)d_in[8];
    const float* Wv  = (const float*)d_in[9];
    const float* bv  = (const float*)d_in[10];
    const float* W1  = (const float*)d_in[11];
    const float* b1  = (const float*)d_in[12];
    const float* bng = (const float*)d_in[13];
    const float* bnb = (const float*)d_in[14];
    const float* bnm = (const float*)d_in[15];
    const float* bnv = (const float*)d_in[16];
    const float* W2  = (const float*)d_in[17];
    const float* b2  = (const float*)d_in[18];
    float* out = (float*)d_out;

    const int n  = in_sizes[1] / NC;
    const int n2 = in_sizes[3] / NC;
    const int mmax = n > n2 ? n : n2;

    const int smem_bytes = 2 * 128 * LDA * 4;   // 69632
    static int attr_set = 0;
    if (!attr_set) {
        cudaFuncSetAttribute(proj_kernel,
                             cudaFuncAttributeMaxDynamicSharedMemorySize,
                             smem_bytes);
        attr_set = 1;
    }

    dim3 pg((mmax + 127) / 128, 3);
    proj_kernel<<<pg, 256, smem_bytes>>>(x, x2, Wq, Wk, Wv, n, n2);
    attn_kernel<<<(n + 7) / 8, 256>>>(p, p2, idx, bq, bk, bv,
                                      W1, b1, bng, bnb, bnm, bnv,
                                      W2, b2, out, n);
}

// round 12
// speedup vs baseline: 1.1419x; 1.1117x over previous
#include <cuda_runtime.h>
#include <mma.h>

using namespace nvcuda;

#define NQ_MAX 50000
#define NC 128
#define NG 8
#define NS 16

// Padded by 128 rows: partial-tile wmma stores at the M edge write into the
// pad instead of the neighboring buffer.
__device__ float g_q[(NQ_MAX + 128) * NC];
__device__ float g_k[(NQ_MAX + 128) * NC];
__device__ float g_v[(NQ_MAX + 128) * NC];

__device__ __forceinline__ float to_tf32(float x) {
    float r;
    asm("cvt.rna.tf32.f32 %0, %1;" : "=f"(r) : "f"(x));
    return r;
}

// ---------------------------------------------------------------------------
// Projection GEMM (tf32 tensor cores) — R4 structure (known 71us plateau).
// Y[m,c] = sum_k X[m,k] * W[c,k]   (biases folded into attn kernel)
// Block tile 128x128, BK=32, 8 warps: 4(M) x 2(N), warp tile 32x64.
// ---------------------------------------------------------------------------
#define LDA 36

__global__ void __launch_bounds__(256) proj_kernel(
    const float* __restrict__ x, const float* __restrict__ x2,
    const float* __restrict__ Wq, const float* __restrict__ Wk,
    const float* __restrict__ Wv,
    int n, int n2)
{
    const float *X, *W;
    float* Y;
    int M;
    if (blockIdx.y == 0)      { X = x;  W = Wq; Y = g_q; M = n;  }
    else if (blockIdx.y == 1) { X = x2; W = Wk; Y = g_k; M = n2; }
    else                      { X = x2; W = Wv; Y = g_v; M = n2; }

    __shared__ float As[128 * LDA];
    __shared__ float Bs[128 * LDA];

    const int t = threadIdx.x;
    const int block_m = blockIdx.x * 128;
    if (block_m >= M) return;

    const int warp = t >> 5;
    const int wm = (warp & 3) * 32;
    const int wn = (warp >> 2) * 64;

    wmma::fragment<wmma::accumulator, 16, 16, 8, float> acc[2][4];
#pragma unroll
    for (int i = 0; i < 2; i++)
#pragma unroll
        for (int j = 0; j < 4; j++) wmma::fill_fragment(acc[i][j], 0.0f);

    for (int k0 = 0; k0 < 128; k0 += 32) {
#pragma unroll
        for (int it = 0; it < 4; it++) {
            int lin = it * 256 + t;
            int r = lin >> 3;
            int c4 = (lin & 7) << 2;
            int gr = block_m + r;
            float4 xv = make_float4(0.f, 0.f, 0.f, 0.f);
            if (gr < M) xv = *(const float4*)(X + (size_t)gr * 128 + k0 + c4);
            As[r * LDA + c4 + 0] = to_tf32(xv.x);
            As[r * LDA + c4 + 1] = to_tf32(xv.y);
            As[r * LDA + c4 + 2] = to_tf32(xv.z);
            As[r * LDA + c4 + 3] = to_tf32(xv.w);
            float4 wv = *(const float4*)(W + (size_t)r * 128 + k0 + c4);
            Bs[r * LDA + c4 + 0] = to_tf32(wv.x);
            Bs[r * LDA + c4 + 1] = to_tf32(wv.y);
            Bs[r * LDA + c4 + 2] = to_tf32(wv.z);
            Bs[r * LDA + c4 + 3] = to_tf32(wv.w);
        }
        __syncthreads();

#pragma unroll
        for (int kk = 0; kk < 32; kk += 8) {
            wmma::fragment<wmma::matrix_a, 16, 16, 8, wmma::precision::tf32, wmma::row_major> a[2];
            wmma::fragment<wmma::matrix_b, 16, 16, 8, wmma::precision::tf32, wmma::col_major> b[4];
#pragma unroll
            for (int i = 0; i < 2; i++)
                wmma::load_matrix_sync(a[i], As + (wm + i * 16) * LDA + kk, LDA);
#pragma unroll
            for (int j = 0; j < 4; j++)
                wmma::load_matrix_sync(b[j], Bs + (wn + j * 16) * LDA + kk, LDA);
#pragma unroll
            for (int i = 0; i < 2; i++)
#pragma unroll
                for (int j = 0; j < 4; j++)
                    wmma::mma_sync(acc[i][j], a[i], b[j], acc[i][j]);
        }
        __syncthreads();
    }

#pragma unroll
    for (int i = 0; i < 2; i++)
#pragma unroll
        for (int j = 0; j < 4; j++)
            wmma::store_matrix_sync(
                Y + (size_t)(block_m + wm + i * 16) * 128 + wn + j * 16,
                acc[i][j], 128, wmma::mem_row_major);
}

// ---------------------------------------------------------------------------
// Fused gather + positional MLP + grouped attention (R11 attn, 74.1us, plus
// tree-shaped softmax reductions). One warp per query. Lane l -> channels
// [4l,4l+4), group g = l>>2. Neighbor MLP hidden computed once by lane
// (l&15), fetched via shfl; butterfly inline per neighbor.
// ---------------------------------------------------------------------------
__global__ void __launch_bounds__(256, 4) attn_kernel(
    const float* __restrict__ p, const float* __restrict__ p2,
    const int* __restrict__ idx,
    const float* __restrict__ bq, const float* __restrict__ bk,
    const float* __restrict__ bv,
    const float* __restrict__ W1, const float* __restrict__ b1,
    const float* __restrict__ bng, const float* __restrict__ bnb,
    const float* __restrict__ bnm, const float* __restrict__ bnv,
    const float* __restrict__ W2, const float* __restrict__ b2,
    float* __restrict__ out, int n)
{
    __shared__ float sA[9];
    __shared__ float sc[3];
    __shared__ float sW2[16][3];
    __shared__ float sb2[16];
    __shared__ float sBg[8];

    const int t = threadIdx.x;
    if (t < 9) {
        int r = t / 3;
        float s = bng[r] * rsqrtf(bnv[r] + 1e-5f);
        sA[t] = s * W1[t];
    }
    if (t < 3) sc[t] = bng[t] * rsqrtf(bnv[t] + 1e-5f) * (b1[t] - bnm[t]) + bnb[t];
    if (t < 48) sW2[t / 3][t % 3] = W2[t];
    if (t < 16) sb2[t] = b2[t];
    if (t < 8) {
        float s = 0.f;
#pragma unroll
        for (int c = 0; c < 16; c++) s += bk[t * 16 + c];
        sBg[t] = s;
    }
    __syncthreads();

    const int warp = t >> 5;
    const int lane = t & 31;
    const int i = blockIdx.x * 8 + warp;
    if (i >= n) return;

    const int g = lane >> 2;
    const float w2q0 = sW2[g][0], w2q1 = sW2[g][1], w2q2 = sW2[g][2], b2q = sb2[g];
    const float w2k0 = sW2[8 + g][0], w2k1 = sW2[8 + g][1], w2k2 = sW2[8 + g][2], b2k = sb2[8 + g];
    const float Bg = sBg[g];

    float4 q4 = *(const float4*)(g_q + (size_t)i * 128 + lane * 4);
    {
        const float4 bq4 = *(const float4*)(bq + lane * 4);
        q4.x += bq4.x; q4.y += bq4.y; q4.z += bq4.z; q4.w += bq4.w;
    }

    float qs, beta;
    {
        const float4 bk4 = *(const float4*)(bk + lane * 4);
        qs   = q4.x + q4.y + q4.z + q4.w;
        beta = bk4.x * q4.x + bk4.y * q4.y + bk4.z * q4.z + bk4.w * q4.w;
        qs   += __shfl_xor_sync(0xffffffffu, qs, 1);
        beta += __shfl_xor_sync(0xffffffffu, beta, 1);
        qs   += __shfl_xor_sync(0xffffffffu, qs, 2);
        beta += __shfl_xor_sync(0xffffffffu, beta, 2);
    }

    int nb[16];
    {
        const int4* ip = (const int4*)(idx + (size_t)i * 16);
#pragma unroll
        for (int s4 = 0; s4 < 4; s4++) {
            int4 v = ip[s4];
            nb[s4 * 4 + 0] = v.x; nb[s4 * 4 + 1] = v.y;
            nb[s4 * 4 + 2] = v.z; nb[s4 * 4 + 3] = v.w;
        }
    }

    // per-neighbor MLP hidden, computed once by lane (l & 15)
    float h0, h1, h2;
    {
        const float px = p[i * 3 + 0], py = p[i * 3 + 1], pz = p[i * 3 + 2];
        const int jm = nb[lane & 15];
        const float rx = p2[jm * 3 + 0] - px;
        const float ry = p2[jm * 3 + 1] - py;
        const float rz = p2[jm * 3 + 2] - pz;
        h0 = fmaxf(fmaf(sA[0], rx, fmaf(sA[1], ry, fmaf(sA[2], rz, sc[0]))), 0.f);
        h1 = fmaxf(fmaf(sA[3], rx, fmaf(sA[4], ry, fmaf(sA[5], rz, sc[1]))), 0.f);
        h2 = fmaxf(fmaf(sA[6], rx, fmaf(sA[7], ry, fmaf(sA[8], rz, sc[2]))), 0.f);
    }

    float logit[16];
#pragma unroll
    for (int s = 0; s < 16; s++) {
        const int j = nb[s];
        const float4 k4 = *(const float4*)(g_k + (size_t)j * 128 + lane * 4);
        float kq = k4.x * q4.x + k4.y * q4.y + k4.z * q4.z + k4.w * q4.w;
        float ks = k4.x + k4.y + k4.z + k4.w;

        const float h0s = __shfl_sync(0xffffffffu, h0, s);
        const float h1s = __shfl_sync(0xffffffffu, h1, s);
        const float h2s = __shfl_sync(0xffffffffu, h2, s);
        const float prq = fmaf(w2q0, h0s, fmaf(w2q1, h1s, fmaf(w2q2, h2s, b2q)));
        const float prk = fmaf(w2k0, h0s, fmaf(w2k1, h1s, fmaf(w2k2, h2s, b2k)));

        float u = fmaf(prq, ks, kq);
        u += __shfl_xor_sync(0xffffffffu, u, 1);
        u += __shfl_xor_sync(0xffffffffu, u, 2);

        logit[s] = 0.25f * (u + beta + prq * Bg + prk * fmaf(16.f, prq, qs));
    }

    // tree max (depth 4 instead of serial depth 15)
    float m8[8];
#pragma unroll
    for (int s = 0; s < 8; s++) m8[s] = fmaxf(logit[s], logit[s + 8]);
    float m4[4];
#pragma unroll
    for (int s = 0; s < 4; s++) m4[s] = fmaxf(m8[s], m8[s + 4]);
    const float mx = fmaxf(fmaxf(m4[0], m4[1]), fmaxf(m4[2], m4[3]));

#pragma unroll
    for (int s = 0; s < 16; s++) logit[s] = __expf(logit[s] - mx);

    // tree sum (depth 4)
    float d8[8];
#pragma unroll
    for (int s = 0; s < 8; s++) d8[s] = logit[s] + logit[s + 8];
    float d4[4];
#pragma unroll
    for (int s = 0; s < 4; s++) d4[s] = d8[s] + d8[s + 4];
    const float denom = (d4[0] + d4[1]) + (d4[2] + d4[3]);
    const float inv = 1.f / denom;

    float4 o = make_float4(0.f, 0.f, 0.f, 0.f);
#pragma unroll
    for (int s = 0; s < 16; s++) {
        const float w = logit[s] * inv;
        const float4 v4 = *(const float4*)(g_v + (size_t)nb[s] * 128 + lane * 4);
        o.x = fmaf(w, v4.x, o.x);
        o.y = fmaf(w, v4.y, o.y);
        o.z = fmaf(w, v4.z, o.z);
        o.w = fmaf(w, v4.w, o.w);
    }
    const float4 bv4 = *(const float4*)(bv + lane * 4);
    o.x += bv4.x; o.y += bv4.y; o.z += bv4.z; o.w += bv4.w;
    *(float4*)(out + (size_t)i * 128 + lane * 4) = o;
}

extern "C" void kernel_launch(void* const* d_in, const int* in_sizes, int n_in,
                              void* d_out, int out_size)
{
    const float* p   = (const float*)d_in[0];
    const float* x   = (const float*)d_in[1];
    const float* p2  = (const float*)d_in[2];
    const float* x2  = (const float*)d_in[3];
    const int*   idx = (const int*)d_in[4];
    const float* Wq  = (const float*)d_in[5];
    const float* bq  = (const float*)d_in[6];
    const float* Wk  = (const float*)d_in[7];
    const float* bk  = (const float*)d_in[8];
    const float* Wv  = (const float*)d_in[9];
    const float* bv  = (const float*)d_in[10];
    const float* W1  = (const float*)d_in[11];
    const float* b1  = (const float*)d_in[12];
    const float* bng = (const float*)d_in[13];
    const float* bnb = (const float*)d_in[14];
    const float* bnm = (const float*)d_in[15];
    const float* bnv = (const float*)d_in[16];
    const float* W2  = (const float*)d_in[17];
    const float* b2  = (const float*)d_in[18];
    float* out = (float*)d_out;

    const int n  = in_sizes[1] / NC;
    const int n2 = in_sizes[3] / NC;
    const int mmax = n > n2 ? n : n2;

    dim3 pg((mmax + 127) / 128, 3);
    proj_kernel<<<pg, 256>>>(x, x2, Wq, Wk, Wv, n, n2);
    attn_kernel<<<(n + 7) / 8, 256>>>(p, p2, idx, bq, bk, bv,
                                      W1, b1, bng, bnb, bnm, bnv,
                                      W2, b2, out, n);
}